// round 1
// baseline (speedup 1.0000x reference)
#include <cuda_runtime.h>
#include <cuda_bf16.h>

#define M_NODES 100000
#define HID     256
#define NREL    6
#define EPR     100000
#define NEDGE   (NREL * EPR)        // 600000
#define KREL    (NREL * HID)        // 1536
#define KTOT    (KREL + HID)        // 1792
#define NGRAPH  128

// -------- scratch (device globals; no allocation allowed) --------
__device__ float g_Agg[(size_t)M_NODES * KREL];   // 614.4 MB: per-node per-relation aggregated (deg-normalized) features
__device__ float g_h0[(size_t)M_NODES * HID];     // 102.4 MB
__device__ float g_h1[(size_t)M_NODES * HID];     // 102.4 MB
__device__ float g_invdeg[M_NODES];
__device__ int   g_deg[M_NODES];
__device__ float g_pooled[NGRAPH * HID];
__device__ int   g_counts[NGRAPH];

// ---------------------------------------------------------------
// h0[n] = concat(type_emb[x_type[n]], sub_emb[x_sub[n]])
__global__ void embed_kernel(const int* __restrict__ x_type, const int* __restrict__ x_sub,
                             const float* __restrict__ temb, const float* __restrict__ semb,
                             float* __restrict__ h0)
{
    int gid = blockIdx.x * 256 + threadIdx.x;
    if (gid < M_NODES * HID) {
        int n = gid >> 8;
        int c = gid & 255;
        h0[gid] = (c < 128) ? temb[x_type[n] * 128 + c]
                            : semb[x_sub[n] * 128 + (c - 128)];
    }
}

// total in-degree per node over all relations
__global__ void degree_kernel(const int* __restrict__ edges, int* __restrict__ deg)
{
    int i = blockIdx.x * 256 + threadIdx.x;
    if (i < NEDGE) {
        int r = i / EPR, e = i % EPR;
        int tgt = edges[r * 2 * EPR + EPR + e];
        atomicAdd(&deg[tgt], 1);
    }
}

__global__ void invdeg_kernel(const int* __restrict__ deg, float* __restrict__ invd)
{
    int i = blockIdx.x * 256 + threadIdx.x;
    if (i < M_NODES) {
        int d = deg[i];
        invd[i] = 1.0f / (float)(d > 1 ? d : 1);
    }
}

// one block (256 threads) per edge: Agg[tgt][r*256 + c] += h[src][c] * invdeg[tgt]
__global__ void scatter_kernel(const int* __restrict__ edges, const float* __restrict__ h,
                               const float* __restrict__ invd, float* __restrict__ Agg)
{
    int el = blockIdx.x;            // 0..NEDGE-1
    int r = el / EPR, e = el % EPR;
    int src = edges[r * 2 * EPR + e];
    int tgt = edges[r * 2 * EPR + EPR + e];
    float w = invd[tgt];
    int c = threadIdx.x;
    float v = h[(size_t)src * HID + c] * w;
    atomicAdd(&Agg[(size_t)tgt * KREL + r * HID + c], v);
}

// ---------------------------------------------------------------
// C[M,256] = relu( [Agg | Hin] (M x 1792) @ [Wrel ; Wself] (1792 x 256) + bias )
// 128x128 block tile, 8x8 per thread, K-tile 16, fp32.
__global__ __launch_bounds__(256, 2)
void gemm_layer(const float* __restrict__ Agg, const float* __restrict__ Hin,
                const float* __restrict__ Wrel, const float* __restrict__ Wself,
                const float* __restrict__ bias, float* __restrict__ Hout)
{
    __shared__ float As[16][128];
    __shared__ float Bs[16][128];

    const int n0 = blockIdx.x * 128;
    const int m0 = blockIdx.y * 128;
    const int tid = threadIdx.x;
    const int tm = tid / 16;        // 0..15
    const int tn = tid % 16;        // 0..15

    // loader coordinates
    const int a_row = tid / 4;          // 0..63
    const int a_col = (tid % 4) * 4;    // 0,4,8,12
    const int b_row = tid / 32;         // 0..7
    const int b_col = (tid % 32) * 4;   // 0..124

    float acc[8][8];
#pragma unroll
    for (int i = 0; i < 8; i++)
#pragma unroll
        for (int j = 0; j < 8; j++) acc[i][j] = 0.0f;

    for (int k0 = 0; k0 < KTOT; k0 += 16) {
        // ---- load A tile (128 x 16), transposed into As[k][m] ----
#pragma unroll
        for (int half = 0; half < 2; ++half) {
            int m = m0 + a_row + half * 64;
            int mm = m < M_NODES ? m : M_NODES - 1;
            const float* src = (k0 < KREL)
                ? (Agg + (size_t)mm * KREL + k0 + a_col)
                : (Hin + (size_t)mm * HID + (k0 - KREL) + a_col);
            float4 v = *(const float4*)src;
            As[a_col + 0][a_row + half * 64] = v.x;
            As[a_col + 1][a_row + half * 64] = v.y;
            As[a_col + 2][a_row + half * 64] = v.z;
            As[a_col + 3][a_row + half * 64] = v.w;
        }
        // ---- load B tile (16 x 128) ----
#pragma unroll
        for (int half = 0; half < 2; ++half) {
            int k = k0 + b_row + half * 8;
            const float* src = (k < KREL)
                ? (Wrel + (size_t)k * HID + n0 + b_col)
                : (Wself + (size_t)(k - KREL) * HID + n0 + b_col);
            float4 v = *(const float4*)src;
            *(float4*)&Bs[b_row + half * 8][b_col] = v;
        }
        __syncthreads();

#pragma unroll
        for (int k = 0; k < 16; ++k) {
            float a[8], b[8];
            *(float4*)&a[0] = *(const float4*)&As[k][tm * 8];
            *(float4*)&a[4] = *(const float4*)&As[k][tm * 8 + 4];
            *(float4*)&b[0] = *(const float4*)&Bs[k][tn * 8];
            *(float4*)&b[4] = *(const float4*)&Bs[k][tn * 8 + 4];
#pragma unroll
            for (int i = 0; i < 8; i++)
#pragma unroll
                for (int j = 0; j < 8; j++)
                    acc[i][j] += a[i] * b[j];
        }
        __syncthreads();
    }

    // epilogue: + bias, relu, store
    const int nbase = n0 + tn * 8;
    float bb[8];
#pragma unroll
    for (int j = 0; j < 8; j++) bb[j] = bias[nbase + j];

#pragma unroll
    for (int i = 0; i < 8; i++) {
        int m = m0 + tm * 8 + i;
        if (m < M_NODES) {
            float4 o0, o1;
            float v;
            v = acc[i][0] + bb[0]; o0.x = v > 0.f ? v : 0.f;
            v = acc[i][1] + bb[1]; o0.y = v > 0.f ? v : 0.f;
            v = acc[i][2] + bb[2]; o0.z = v > 0.f ? v : 0.f;
            v = acc[i][3] + bb[3]; o0.w = v > 0.f ? v : 0.f;
            v = acc[i][4] + bb[4]; o1.x = v > 0.f ? v : 0.f;
            v = acc[i][5] + bb[5]; o1.y = v > 0.f ? v : 0.f;
            v = acc[i][6] + bb[6]; o1.z = v > 0.f ? v : 0.f;
            v = acc[i][7] + bb[7]; o1.w = v > 0.f ? v : 0.f;
            *(float4*)&Hout[(size_t)m * HID + nbase]     = o0;
            *(float4*)&Hout[(size_t)m * HID + nbase + 4] = o1;
        }
    }
}

// ---------------------------------------------------------------
// counts per graph via binary search (batch_ids sorted)
__global__ void count_kernel(const int* __restrict__ bids, int* __restrict__ counts)
{
    int g = threadIdx.x;
    if (g >= NGRAPH) return;
    int lo = 0, hi = M_NODES;
    while (lo < hi) { int mid = (lo + hi) >> 1; if (bids[mid] < g) lo = mid + 1; else hi = mid; }
    int start = lo;
    lo = 0; hi = M_NODES;
    while (lo < hi) { int mid = (lo + hi) >> 1; if (bids[mid] <= g) lo = mid + 1; else hi = mid; }
    counts[g] = lo - start;
}

// run-length pooled sum exploiting sorted batch_ids; thread = feature column
__global__ void pool_sum_kernel(const float* __restrict__ h, const int* __restrict__ bids,
                                float* __restrict__ pooled)
{
    int c = threadIdx.x;
    int n_start = blockIdx.x * 256;
    int n_end = n_start + 256;
    if (n_end > M_NODES) n_end = M_NODES;
    if (n_start >= M_NODES) return;

    int cur = bids[n_start];
    float acc = 0.0f;
    for (int n = n_start; n < n_end; n++) {
        int g = bids[n];
        if (g != cur) {
            atomicAdd(&pooled[cur * HID + c], acc);
            acc = 0.0f;
            cur = g;
        }
        acc += h[(size_t)n * HID + c];
    }
    atomicAdd(&pooled[cur * HID + c], acc);
}

// final MLP: out[g] = relu(pooled[g]/cnt @ pW1 + pb1) @ pW2 + pb2
__global__ void mlp_kernel(const float* __restrict__ pooled, const int* __restrict__ counts,
                           const float* __restrict__ pW1, const float* __restrict__ pb1,
                           const float* __restrict__ pW2, const float* __restrict__ pb2,
                           float* __restrict__ out)
{
    __shared__ float p[HID];
    __shared__ float t[HID];
    int g = blockIdx.x;
    int d = threadIdx.x;

    int cn = counts[g];
    float inv = 1.0f / (float)(cn > 1 ? cn : 1);
    p[d] = pooled[g * HID + d] * inv;
    __syncthreads();

    float a = pb1[d];
#pragma unroll 8
    for (int k = 0; k < HID; k++) a += p[k] * pW1[k * HID + d];
    t[d] = a > 0.f ? a : 0.f;
    __syncthreads();

    float o = pb2[d];
#pragma unroll 8
    for (int k = 0; k < HID; k++) o += t[k] * pW2[k * HID + d];
    out[g * HID + d] = o;
}

// ---------------------------------------------------------------
extern "C" void kernel_launch(void* const* d_in, const int* in_sizes, int n_in,
                              void* d_out, int out_size)
{
    const int*   x_type = (const int*)d_in[0];
    const int*   x_sub  = (const int*)d_in[1];
    const int*   edges  = (const int*)d_in[2];
    const int*   bids   = (const int*)d_in[3];
    // d_in[4] = n_graphs (compile-time 128)
    const float* temb   = (const float*)d_in[5];
    const float* semb   = (const float*)d_in[6];
    const float* Wrel0  = (const float*)d_in[7];
    const float* Wself0 = (const float*)d_in[8];
    const float* b0     = (const float*)d_in[9];
    const float* Wrel1  = (const float*)d_in[10];
    const float* Wself1 = (const float*)d_in[11];
    const float* b1     = (const float*)d_in[12];
    const float* pW1    = (const float*)d_in[13];
    const float* pb1    = (const float*)d_in[14];
    const float* pW2    = (const float*)d_in[15];
    const float* pb2    = (const float*)d_in[16];
    float* out = (float*)d_out;

    void *pAgg, *ph0, *ph1, *pinv, *pdeg, *ppooled, *pcnt;
    cudaGetSymbolAddress(&pAgg, g_Agg);
    cudaGetSymbolAddress(&ph0, g_h0);
    cudaGetSymbolAddress(&ph1, g_h1);
    cudaGetSymbolAddress(&pinv, g_invdeg);
    cudaGetSymbolAddress(&pdeg, g_deg);
    cudaGetSymbolAddress(&ppooled, g_pooled);
    cudaGetSymbolAddress(&pcnt, g_counts);

    cudaMemsetAsync(pdeg, 0, M_NODES * sizeof(int));
    cudaMemsetAsync(ppooled, 0, NGRAPH * HID * sizeof(float));

    embed_kernel<<<(M_NODES * HID + 255) / 256, 256>>>(x_type, x_sub, temb, semb, (float*)ph0);
    degree_kernel<<<(NEDGE + 255) / 256, 256>>>(edges, (int*)pdeg);
    invdeg_kernel<<<(M_NODES + 255) / 256, 256>>>((const int*)pdeg, (float*)pinv);

    dim3 ggrid(2, (M_NODES + 127) / 128);

    // layer 0: h0 -> h1
    cudaMemsetAsync(pAgg, 0, (size_t)M_NODES * KREL * sizeof(float));
    scatter_kernel<<<NEDGE, 256>>>(edges, (const float*)ph0, (const float*)pinv, (float*)pAgg);
    gemm_layer<<<ggrid, 256>>>((const float*)pAgg, (const float*)ph0, Wrel0, Wself0, b0, (float*)ph1);

    // layer 1: h1 -> h0 (reuse buffer)
    cudaMemsetAsync(pAgg, 0, (size_t)M_NODES * KREL * sizeof(float));
    scatter_kernel<<<NEDGE, 256>>>(edges, (const float*)ph1, (const float*)pinv, (float*)pAgg);
    gemm_layer<<<ggrid, 256>>>((const float*)pAgg, (const float*)ph1, Wrel1, Wself1, b1, (float*)ph0);

    // pool + MLP
    count_kernel<<<1, 128>>>(bids, (int*)pcnt);
    pool_sum_kernel<<<(M_NODES + 255) / 256, 256>>>((const float*)ph0, bids, (float*)ppooled);
    mlp_kernel<<<NGRAPH, 256>>>((const float*)ppooled, (const int*)pcnt, pW1, pb1, pW2, pb2, out);
}

// round 3
// speedup vs baseline: 2.6143x; 2.6143x over previous
#include <cuda_runtime.h>
#include <cuda_bf16.h>

#define M_NODES 100000
#define HID     256
#define NREL    6
#define EPR     100000
#define NEDGE   (NREL * EPR)        // 600000
#define NMSG    1792                // 6*256 rel msgs + 256 self
#define NGRAPH  128

#define BM 128
#define BN 128
#define BK 64
#define KSPLIT 768                  // 3 * 256 (bf16 hi/lo split)
#define NCHUNK (KSPLIT / BK)        // 12
#define GSMEM  (2 * (BM + BN) * BK * 2)   // 2 stages * (16KB + 16KB) = 65536

// ---------------- scratch (device globals; no allocation allowed) ----------------
__device__ float          g_hA[(size_t)M_NODES * HID];
__device__ float          g_hB[(size_t)M_NODES * HID];
__device__ float          g_msg[(size_t)M_NODES * NMSG];   // 716.8 MB
__device__ float          g_acc[(size_t)M_NODES * HID];    // 102.4 MB (fits L2)
__device__ __nv_bfloat16  g_Ahi[(size_t)M_NODES * HID];
__device__ __nv_bfloat16  g_Alo[(size_t)M_NODES * HID];
__device__ __nv_bfloat16  g_WtHi[NMSG * HID];              // [n][k]
__device__ __nv_bfloat16  g_WtLo[NMSG * HID];
__device__ float          g_invdeg[M_NODES];
__device__ int            g_deg[M_NODES];
__device__ float          g_pooled[NGRAPH * HID];
__device__ int            g_counts[NGRAPH];

// ---------------- PTX helpers (baseline ISA only; no 'a'-gated features) ----------------
__device__ __forceinline__ unsigned su32(const void* p) {
    return (unsigned)__cvta_generic_to_shared(p);
}
__device__ __forceinline__ void cp16(void* sm, const void* gm) {
    asm volatile("cp.async.cg.shared.global [%0], [%1], 16;" :: "r"(su32(sm)), "l"(gm));
}
#define CP_COMMIT() asm volatile("cp.async.commit_group;" ::: "memory")
#define CP_WAIT(n)  asm volatile("cp.async.wait_group %0;" :: "n"(n) : "memory")

__device__ __forceinline__ void ldsm4(unsigned* r, unsigned addr) {
    asm volatile("ldmatrix.sync.aligned.m8n8.x4.shared.b16 {%0,%1,%2,%3}, [%4];"
                 : "=r"(r[0]), "=r"(r[1]), "=r"(r[2]), "=r"(r[3]) : "r"(addr));
}
__device__ __forceinline__ void mma16816(float* c, const unsigned* a, unsigned b0, unsigned b1) {
    asm volatile("mma.sync.aligned.m16n8k16.row.col.f32.bf16.bf16.f32 "
                 "{%0,%1,%2,%3}, {%4,%5,%6,%7}, {%8,%9}, {%0,%1,%2,%3};"
                 : "+f"(c[0]), "+f"(c[1]), "+f"(c[2]), "+f"(c[3])
                 : "r"(a[0]), "r"(a[1]), "r"(a[2]), "r"(a[3]), "r"(b0), "r"(b1));
}
__device__ __forceinline__ unsigned swz(unsigned off) {   // 128B-row, 16B-unit XOR swizzle
    return off ^ ((off >> 3) & 0x70);
}

// ---------------- small kernels ----------------
__global__ void embed_kernel(const int* __restrict__ x_type, const int* __restrict__ x_sub,
                             const float* __restrict__ temb, const float* __restrict__ semb,
                             float* __restrict__ h0)
{
    int gid = blockIdx.x * 256 + threadIdx.x;
    if (gid < M_NODES * HID) {
        int n = gid >> 8, c = gid & 255;
        h0[gid] = (c < 128) ? temb[x_type[n] * 128 + c] : semb[x_sub[n] * 128 + (c - 128)];
    }
}

__global__ void degree_kernel(const int* __restrict__ edges, int* __restrict__ deg)
{
    int i = blockIdx.x * 256 + threadIdx.x;
    if (i < NEDGE) {
        int r = i / EPR, e = i % EPR;
        atomicAdd(&deg[edges[r * 2 * EPR + EPR + e]], 1);
    }
}

__global__ void invdeg_kernel(const int* __restrict__ deg, float* __restrict__ invd)
{
    int i = blockIdx.x * 256 + threadIdx.x;
    if (i < M_NODES) {
        int d = deg[i];
        invd[i] = 1.0f / (float)(d > 1 ? d : 1);
    }
}

__global__ void splitA_kernel(const float* __restrict__ h,
                              __nv_bfloat16* __restrict__ hi, __nv_bfloat16* __restrict__ lo)
{
    int i = blockIdx.x * 256 + threadIdx.x;
    if (i < M_NODES * HID) {
        float x = h[i];
        __nv_bfloat16 xh = __float2bfloat16(x);
        hi[i] = xh;
        lo[i] = __float2bfloat16(x - __bfloat162float(xh));
    }
}

__global__ void splitW_kernel(const float* __restrict__ Wrel, const float* __restrict__ Wself,
                              __nv_bfloat16* __restrict__ WtHi, __nv_bfloat16* __restrict__ WtLo)
{
    int idx = blockIdx.x * 256 + threadIdx.x;
    if (idx < NMSG * HID) {
        int n = idx >> 8, k = idx & 255;
        float v = (n < 1536) ? Wrel[(((n >> 8) * 256) + k) * 256 + (n & 255)]
                             : Wself[k * 256 + (n & 255)];
        __nv_bfloat16 vh = __float2bfloat16(v);
        WtHi[idx] = vh;
        WtLo[idx] = __float2bfloat16(v - __bfloat162float(vh));
    }
}

// ---------------- HMMA GEMM: msg[M,1792] = h[M,256] @ Wcat  (split-bf16, K'=768) ----------------
// 128x128 tile, 256 threads (8 warps as 4m x 2n), warp tile 32x64, m16n8k16.
__global__ __launch_bounds__(256, 2)
void gemm_mma(const __nv_bfloat16* __restrict__ Ahi, const __nv_bfloat16* __restrict__ Alo,
              const __nv_bfloat16* __restrict__ WtHi, const __nv_bfloat16* __restrict__ WtLo,
              float* __restrict__ msg)
{
    extern __shared__ unsigned char smraw[];
    const int tid  = threadIdx.x;
    const int lane = tid & 31;
    const int wid  = tid >> 5;
    const int wm   = wid & 3;        // 0..3  (m)
    const int wn   = wid >> 2;       // 0..1  (n)
    const int m0   = blockIdx.y * BM;
    const int n0   = blockIdx.x * BN;

    const int lrow = tid >> 3;       // 0..31
    const int lseg = tid & 7;        // 16B segment in 128B row

    int amrow[4];
#pragma unroll
    for (int p = 0; p < 4; p++) {
        int m = m0 + lrow + p * 32;
        amrow[p] = m < M_NODES ? m : M_NODES - 1;
    }

    float acc[2][8][4];
#pragma unroll
    for (int mi = 0; mi < 2; mi++)
#pragma unroll
        for (int ni = 0; ni < 8; ni++)
#pragma unroll
            for (int j = 0; j < 4; j++) acc[mi][ni][j] = 0.0f;

    // stage base addresses
    unsigned aS[2], bS[2];
    aS[0] = su32(smraw);            bS[0] = su32(smraw + 16384);
    aS[1] = su32(smraw + 32768);    bS[1] = su32(smraw + 49152);

    // -------- issue cp.async loads for chunk c into stage st --------
    auto issue = [&](int c, int st) {
        int sel  = c >> 2;                    // 0:hi*hi  1:hi*lo  2:lo*hi
        int koff = (c & 3) * BK;
        const __nv_bfloat16* Ag = (sel == 2) ? Alo  : Ahi;
        const __nv_bfloat16* Bg = (sel == 1) ? WtLo : WtHi;
        unsigned char* As = smraw + st * 32768;
        unsigned char* Bs = smraw + st * 32768 + 16384;
#pragma unroll
        for (int p = 0; p < 4; p++) {
            int row = lrow + p * 32;
            unsigned so = swz((unsigned)(row * 128 + lseg * 16));
            cp16(As + so, Ag + (size_t)amrow[p] * HID + koff + lseg * 8);
            cp16(Bs + so, Bg + (size_t)(n0 + row) * HID + koff + lseg * 8);
        }
        CP_COMMIT();
    };

    issue(0, 0);

    for (int c = 0; c < NCHUNK; ++c) {
        int st = c & 1;
        if (c + 1 < NCHUNK) { issue(c + 1, st ^ 1); CP_WAIT(1); }
        else                { CP_WAIT(0); }
        __syncthreads();

        unsigned ab = aS[st], bb = bS[st];
#pragma unroll
        for (int ks = 0; ks < 4; ++ks) {
            unsigned a[2][4], b[4][4];
#pragma unroll
            for (int mi = 0; mi < 2; mi++) {
                int row = wm * 32 + mi * 16 + (lane & 15);
                unsigned off = (unsigned)(row * 128 + ks * 32 + (lane >> 4) * 16);
                ldsm4(a[mi], ab + swz(off));
            }
#pragma unroll
            for (int nj = 0; nj < 4; nj++) {
                int q = lane >> 3, r = lane & 7;
                int nrow = wn * 64 + nj * 16 + (q >> 1) * 8 + r;
                unsigned off = (unsigned)(nrow * 128 + ks * 32 + (q & 1) * 16);
                ldsm4(b[nj], bb + swz(off));
            }
#pragma unroll
            for (int mi = 0; mi < 2; mi++)
#pragma unroll
                for (int ni = 0; ni < 8; ni++)
                    mma16816(acc[mi][ni], a[mi], b[ni >> 1][(ni & 1) * 2], b[ni >> 1][(ni & 1) * 2 + 1]);
        }
        __syncthreads();
    }

    // -------- epilogue: direct float2 stores (32B sectors per lane quad) --------
    const int cb = n0 + wn * 64 + (lane & 3) * 2;
#pragma unroll
    for (int mi = 0; mi < 2; mi++) {
        int r0 = m0 + wm * 32 + mi * 16 + (lane >> 2);
        int r1 = r0 + 8;
        if (r0 < M_NODES) {
            float* dst = msg + (size_t)r0 * NMSG + cb;
#pragma unroll
            for (int ni = 0; ni < 8; ni++)
                *(float2*)(dst + ni * 8) = make_float2(acc[mi][ni][0], acc[mi][ni][1]);
        }
        if (r1 < M_NODES) {
            float* dst = msg + (size_t)r1 * NMSG + cb;
#pragma unroll
            for (int ni = 0; ni < 8; ni++)
                *(float2*)(dst + ni * 8) = make_float2(acc[mi][ni][2], acc[mi][ni][3]);
        }
    }
}

// ---------------- scatter: acc[tgt] += msg[src, r*256 : +256]  (float4 red) ----------------
__global__ void scatter_kernel(const int* __restrict__ edges, const float* __restrict__ msg,
                               float* __restrict__ acc)
{
    int e = blockIdx.x * 4 + (threadIdx.x >> 6);
    int q = threadIdx.x & 63;
    int r = e / EPR, idx = e % EPR;
    int src = edges[r * 2 * EPR + idx];
    int tgt = edges[r * 2 * EPR + EPR + idx];
    float4 v = *(const float4*)(msg + (size_t)src * NMSG + r * HID + q * 4);
    float* p = acc + (size_t)tgt * HID + q * 4;
    asm volatile("red.global.add.v4.f32 [%0], {%1, %2, %3, %4};"
                 :: "l"(p), "f"(v.x), "f"(v.y), "f"(v.z), "f"(v.w) : "memory");
}

// ---------------- combine: h_next = relu(acc*invdeg + msg_self + bias) ----------------
__global__ void combine_kernel(const float* __restrict__ acc, const float* __restrict__ msg,
                               const float* __restrict__ invd, const float* __restrict__ bias,
                               float* __restrict__ hout)
{
    int gid = blockIdx.x * 256 + threadIdx.x;
    if (gid < M_NODES * (HID / 4)) {
        int n = gid >> 6, q = gid & 63;
        float w = invd[n];
        float4 a = *(const float4*)(acc + (size_t)gid * 4);
        float4 s = *(const float4*)(msg + (size_t)n * NMSG + 1536 + q * 4);
        float4 bb = *(const float4*)(bias + q * 4);
        float4 o;
        o.x = fmaxf(a.x * w + s.x + bb.x, 0.f);
        o.y = fmaxf(a.y * w + s.y + bb.y, 0.f);
        o.z = fmaxf(a.z * w + s.z + bb.z, 0.f);
        o.w = fmaxf(a.w * w + s.w + bb.w, 0.f);
        *(float4*)(hout + (size_t)gid * 4) = o;
    }
}

// ---------------- pooling + MLP ----------------
__global__ void count_kernel(const int* __restrict__ bids, int* __restrict__ counts)
{
    int g = threadIdx.x;
    if (g >= NGRAPH) return;
    int lo = 0, hi = M_NODES;
    while (lo < hi) { int mid = (lo + hi) >> 1; if (bids[mid] < g) lo = mid + 1; else hi = mid; }
    int start = lo;
    lo = 0; hi = M_NODES;
    while (lo < hi) { int mid = (lo + hi) >> 1; if (bids[mid] <= g) lo = mid + 1; else hi = mid; }
    counts[g] = lo - start;
}

__global__ void pool_sum_kernel(const float* __restrict__ h, const int* __restrict__ bids,
                                float* __restrict__ pooled)
{
    int c = threadIdx.x;
    int n_start = blockIdx.x * 256;
    int n_end = n_start + 256;
    if (n_end > M_NODES) n_end = M_NODES;
    if (n_start >= M_NODES) return;
    int cur = bids[n_start];
    float acc = 0.0f;
    for (int n = n_start; n < n_end; n++) {
        int g = bids[n];
        if (g != cur) { atomicAdd(&pooled[cur * HID + c], acc); acc = 0.0f; cur = g; }
        acc += h[(size_t)n * HID + c];
    }
    atomicAdd(&pooled[cur * HID + c], acc);
}

__global__ void mlp_kernel(const float* __restrict__ pooled, const int* __restrict__ counts,
                           const float* __restrict__ pW1, const float* __restrict__ pb1,
                           const float* __restrict__ pW2, const float* __restrict__ pb2,
                           float* __restrict__ out)
{
    __shared__ float p[HID];
    __shared__ float t[HID];
    int g = blockIdx.x, d = threadIdx.x;
    int cn = counts[g];
    float inv = 1.0f / (float)(cn > 1 ? cn : 1);
    p[d] = pooled[g * HID + d] * inv;
    __syncthreads();
    float a = pb1[d];
#pragma unroll 8
    for (int k = 0; k < HID; k++) a += p[k] * pW1[k * HID + d];
    t[d] = a > 0.f ? a : 0.f;
    __syncthreads();
    float o = pb2[d];
#pragma unroll 8
    for (int k = 0; k < HID; k++) o += t[k] * pW2[k * HID + d];
    out[g * HID + d] = o;
}

// ---------------------------------------------------------------
extern "C" void kernel_launch(void* const* d_in, const int* in_sizes, int n_in,
                              void* d_out, int out_size)
{
    const int*   x_type = (const int*)d_in[0];
    const int*   x_sub  = (const int*)d_in[1];
    const int*   edges  = (const int*)d_in[2];
    const int*   bids   = (const int*)d_in[3];
    const float* temb   = (const float*)d_in[5];
    const float* semb   = (const float*)d_in[6];
    const float* Wrel0  = (const float*)d_in[7];
    const float* Wself0 = (const float*)d_in[8];
    const float* b0     = (const float*)d_in[9];
    const float* Wrel1  = (const float*)d_in[10];
    const float* Wself1 = (const float*)d_in[11];
    const float* b1     = (const float*)d_in[12];
    const float* pW1    = (const float*)d_in[13];
    const float* pb1    = (const float*)d_in[14];
    const float* pW2    = (const float*)d_in[15];
    const float* pb2    = (const float*)d_in[16];
    float* out = (float*)d_out;

    void *phA, *phB, *pmsg, *pacc, *pAhi, *pAlo, *pWtHi, *pWtLo, *pinv, *pdeg, *ppooled, *pcnt;
    cudaGetSymbolAddress(&phA, g_hA);
    cudaGetSymbolAddress(&phB, g_hB);
    cudaGetSymbolAddress(&pmsg, g_msg);
    cudaGetSymbolAddress(&pacc, g_acc);
    cudaGetSymbolAddress(&pAhi, g_Ahi);
    cudaGetSymbolAddress(&pAlo, g_Alo);
    cudaGetSymbolAddress(&pWtHi, g_WtHi);
    cudaGetSymbolAddress(&pWtLo, g_WtLo);
    cudaGetSymbolAddress(&pinv, g_invdeg);
    cudaGetSymbolAddress(&pdeg, g_deg);
    cudaGetSymbolAddress(&ppooled, g_pooled);
    cudaGetSymbolAddress(&pcnt, g_counts);

    cudaFuncSetAttribute(gemm_mma, cudaFuncAttributeMaxDynamicSharedMemorySize, GSMEM);

    cudaMemsetAsync(pdeg, 0, M_NODES * sizeof(int));
    cudaMemsetAsync(ppooled, 0, NGRAPH * HID * sizeof(float));

    embed_kernel<<<(M_NODES * HID + 255) / 256, 256>>>(x_type, x_sub, temb, semb, (float*)phA);
    degree_kernel<<<(NEDGE + 255) / 256, 256>>>(edges, (int*)pdeg);
    invdeg_kernel<<<(M_NODES + 255) / 256, 256>>>((const int*)pdeg, (float*)pinv);

    dim3 ggrid(NMSG / BN, (M_NODES + BM - 1) / BM);   // (14, 782)

    // ---- layer 0: hA -> hB ----
    splitW_kernel<<<(NMSG * HID + 255) / 256, 256>>>(Wrel0, Wself0, (__nv_bfloat16*)pWtHi, (__nv_bfloat16*)pWtLo);
    splitA_kernel<<<(M_NODES * HID + 255) / 256, 256>>>((const float*)phA, (__nv_bfloat16*)pAhi, (__nv_bfloat16*)pAlo);
    gemm_mma<<<ggrid, 256, GSMEM>>>((const __nv_bfloat16*)pAhi, (const __nv_bfloat16*)pAlo,
                                    (const __nv_bfloat16*)pWtHi, (const __nv_bfloat16*)pWtLo, (float*)pmsg);
    cudaMemsetAsync(pacc, 0, (size_t)M_NODES * HID * sizeof(float));
    scatter_kernel<<<NEDGE / 4, 256>>>(edges, (const float*)pmsg, (float*)pacc);
    combine_kernel<<<(M_NODES * (HID / 4) + 255) / 256, 256>>>((const float*)pacc, (const float*)pmsg,
                                                               (const float*)pinv, b0, (float*)phB);

    // ---- layer 1: hB -> hA ----
    splitW_kernel<<<(NMSG * HID + 255) / 256, 256>>>(Wrel1, Wself1, (__nv_bfloat16*)pWtHi, (__nv_bfloat16*)pWtLo);
    splitA_kernel<<<(M_NODES * HID + 255) / 256, 256>>>((const float*)phB, (__nv_bfloat16*)pAhi, (__nv_bfloat16*)pAlo);
    gemm_mma<<<ggrid, 256, GSMEM>>>((const __nv_bfloat16*)pAhi, (const __nv_bfloat16*)pAlo,
                                    (const __nv_bfloat16*)pWtHi, (const __nv_bfloat16*)pWtLo, (float*)pmsg);
    cudaMemsetAsync(pacc, 0, (size_t)M_NODES * HID * sizeof(float));
    scatter_kernel<<<NEDGE / 4, 256>>>(edges, (const float*)pmsg, (float*)pacc);
    combine_kernel<<<(M_NODES * (HID / 4) + 255) / 256, 256>>>((const float*)pacc, (const float*)pmsg,
                                                               (const float*)pinv, b1, (float*)phA);

    // ---- pool + MLP ----
    count_kernel<<<1, 128>>>(bids, (int*)pcnt);
    pool_sum_kernel<<<(M_NODES + 255) / 256, 256>>>((const float*)phA, bids, (float*)ppooled);
    mlp_kernel<<<NGRAPH, 256>>>((const float*)ppooled, (const int*)pcnt, pW1, pb1, pW2, pb2, out);
}

// round 4
// speedup vs baseline: 4.7467x; 1.8156x over previous
#include <cuda_runtime.h>
#include <cuda_fp16.h>

#define M_NODES 100000
#define HID     256
#define NREL    6
#define EPR     100000
#define NEDGE   (NREL * EPR)        // 600000
#define NMSG    1792                // 6*256 rel msgs + 256 self
#define NGRAPH  128

#define BM 128
#define BN 128
#define BK 64
#define NCHUNK (HID / BK)           // 4  (single fp16 pass, K=256)
#define GSMEM  (2 * (BM + BN) * BK * 2)   // 2 stages * (16KB+16KB) = 65536

// ---------------- scratch (device globals; no allocation allowed) ----------------
__device__ __half  g_hA16[(size_t)M_NODES * HID];      // 51.2 MB
__device__ __half  g_hB16[(size_t)M_NODES * HID];      // 51.2 MB
__device__ __half  g_msg[(size_t)M_NODES * NMSG];      // 358.4 MB
__device__ float   g_acc[(size_t)M_NODES * HID];       // 102.4 MB (L2-resident target)
__device__ __half  g_Wt[NMSG * HID];                   // [n][k] transposed fp16
__device__ float   g_invdeg[M_NODES];
__device__ int     g_deg[M_NODES];
__device__ float   g_pooled[NGRAPH * HID];
__device__ int     g_counts[NGRAPH];

// ---------------- PTX helpers (baseline ISA; nothing 'a'-gated) ----------------
__device__ __forceinline__ unsigned su32(const void* p) {
    return (unsigned)__cvta_generic_to_shared(p);
}
__device__ __forceinline__ void cp16(void* sm, const void* gm) {
    asm volatile("cp.async.cg.shared.global [%0], [%1], 16;" :: "r"(su32(sm)), "l"(gm));
}
#define CP_COMMIT() asm volatile("cp.async.commit_group;" ::: "memory")
#define CP_WAIT(n)  asm volatile("cp.async.wait_group %0;" :: "n"(n) : "memory")

__device__ __forceinline__ void ldsm4(unsigned* r, unsigned addr) {
    asm volatile("ldmatrix.sync.aligned.m8n8.x4.shared.b16 {%0,%1,%2,%3}, [%4];"
                 : "=r"(r[0]), "=r"(r[1]), "=r"(r[2]), "=r"(r[3]) : "r"(addr));
}
__device__ __forceinline__ void mma16816(float* c, const unsigned* a, unsigned b0, unsigned b1) {
    asm volatile("mma.sync.aligned.m16n8k16.row.col.f32.f16.f16.f32 "
                 "{%0,%1,%2,%3}, {%4,%5,%6,%7}, {%8,%9}, {%0,%1,%2,%3};"
                 : "+f"(c[0]), "+f"(c[1]), "+f"(c[2]), "+f"(c[3])
                 : "r"(a[0]), "r"(a[1]), "r"(a[2]), "r"(a[3]), "r"(b0), "r"(b1));
}
__device__ __forceinline__ unsigned swz(unsigned off) {   // 128B-row, 16B-unit XOR swizzle
    return off ^ ((off >> 3) & 0x70);
}

// ---------------- small kernels ----------------
// h0 in fp16 directly: concat(type_emb, sub_emb)
__global__ void embed_kernel(const int* __restrict__ x_type, const int* __restrict__ x_sub,
                             const float* __restrict__ temb, const float* __restrict__ semb,
                             __half* __restrict__ h0)
{
    int gid = blockIdx.x * 256 + threadIdx.x;
    if (gid < M_NODES * HID) {
        int n = gid >> 8, c = gid & 255;
        float v = (c < 128) ? temb[x_type[n] * 128 + c] : semb[x_sub[n] * 128 + (c - 128)];
        h0[gid] = __float2half_rn(v);
    }
}

__global__ void degree_kernel(const int* __restrict__ edges, int* __restrict__ deg)
{
    int i = blockIdx.x * 256 + threadIdx.x;
    if (i < NEDGE) {
        int r = i / EPR, e = i % EPR;
        atomicAdd(&deg[edges[r * 2 * EPR + EPR + e]], 1);
    }
}

__global__ void invdeg_kernel(const int* __restrict__ deg, float* __restrict__ invd)
{
    int i = blockIdx.x * 256 + threadIdx.x;
    if (i < M_NODES) {
        int d = deg[i];
        invd[i] = 1.0f / (float)(d > 1 ? d : 1);
    }
}

// Wt[n][k] fp16:  n<1536 -> Wrel[n>>8][k][n&255], else Wself[k][n&255]
__global__ void convW_kernel(const float* __restrict__ Wrel, const float* __restrict__ Wself,
                             __half* __restrict__ Wt)
{
    int idx = blockIdx.x * 256 + threadIdx.x;
    if (idx < NMSG * HID) {
        int n = idx >> 8, k = idx & 255;
        float v = (n < 1536) ? Wrel[(((n >> 8) * 256) + k) * 256 + (n & 255)]
                             : Wself[k * 256 + (n & 255)];
        Wt[idx] = __float2half_rn(v);
    }
}

// ---------------- HMMA GEMM: msg[M,1792] (fp16) = h[M,256] @ Wcat, fp32 accum ----------------
// 128x128 tile, 256 threads (8 warps as 4m x 2n), warp tile 32x64, m16n8k16 fp16.
__global__ __launch_bounds__(256, 2)
void gemm_mma(const __half* __restrict__ A, const __half* __restrict__ Wt,
              __half* __restrict__ msg)
{
    extern __shared__ unsigned char smraw[];
    const int tid  = threadIdx.x;
    const int lane = tid & 31;
    const int wid  = tid >> 5;
    const int wm   = wid & 3;
    const int wn   = wid >> 2;
    const int m0   = blockIdx.y * BM;
    const int n0   = blockIdx.x * BN;

    const int lrow = tid >> 3;       // 0..31
    const int lseg = tid & 7;        // 16B segment in 128B row

    int amrow[4];
#pragma unroll
    for (int p = 0; p < 4; p++) {
        int m = m0 + lrow + p * 32;
        amrow[p] = m < M_NODES ? m : M_NODES - 1;
    }

    float acc[2][8][4];
#pragma unroll
    for (int mi = 0; mi < 2; mi++)
#pragma unroll
        for (int ni = 0; ni < 8; ni++)
#pragma unroll
            for (int j = 0; j < 4; j++) acc[mi][ni][j] = 0.0f;

    unsigned aS[2], bS[2];
    aS[0] = su32(smraw);            bS[0] = su32(smraw + 16384);
    aS[1] = su32(smraw + 32768);    bS[1] = su32(smraw + 49152);

    auto issue = [&](int c, int st) {
        int koff = c * BK;
        unsigned char* As = smraw + st * 32768;
        unsigned char* Bs = smraw + st * 32768 + 16384;
#pragma unroll
        for (int p = 0; p < 4; p++) {
            int row = lrow + p * 32;
            unsigned so = swz((unsigned)(row * 128 + lseg * 16));
            cp16(As + so, A  + (size_t)amrow[p] * HID + koff + lseg * 8);
            cp16(Bs + so, Wt + (size_t)(n0 + row) * HID + koff + lseg * 8);
        }
        CP_COMMIT();
    };

    issue(0, 0);

    for (int c = 0; c < NCHUNK; ++c) {
        int st = c & 1;
        if (c + 1 < NCHUNK) { issue(c + 1, st ^ 1); CP_WAIT(1); }
        else                { CP_WAIT(0); }
        __syncthreads();

        unsigned ab = aS[st], bb = bS[st];
#pragma unroll
        for (int ks = 0; ks < 4; ++ks) {
            unsigned a[2][4], b[4][4];
#pragma unroll
            for (int mi = 0; mi < 2; mi++) {
                int row = wm * 32 + mi * 16 + (lane & 15);
                unsigned off = (unsigned)(row * 128 + ks * 32 + (lane >> 4) * 16);
                ldsm4(a[mi], ab + swz(off));
            }
#pragma unroll
            for (int nj = 0; nj < 4; nj++) {
                int q = lane >> 3, r = lane & 7;
                int nrow = wn * 64 + nj * 16 + (q >> 1) * 8 + r;
                unsigned off = (unsigned)(nrow * 128 + ks * 32 + (q & 1) * 16);
                ldsm4(b[nj], bb + swz(off));
            }
#pragma unroll
            for (int mi = 0; mi < 2; mi++)
#pragma unroll
                for (int ni = 0; ni < 8; ni++)
                    mma16816(acc[mi][ni], a[mi], b[ni >> 1][(ni & 1) * 2], b[ni >> 1][(ni & 1) * 2 + 1]);
        }
        __syncthreads();
    }

    // epilogue: fp32 acc -> fp16 half2 stores
    const int cb = n0 + wn * 64 + (lane & 3) * 2;
#pragma unroll
    for (int mi = 0; mi < 2; mi++) {
        int r0 = m0 + wm * 32 + mi * 16 + (lane >> 2);
        int r1 = r0 + 8;
        if (r0 < M_NODES) {
            __half* dst = msg + (size_t)r0 * NMSG + cb;
#pragma unroll
            for (int ni = 0; ni < 8; ni++)
                *(__half2*)(dst + ni * 8) = __floats2half2_rn(acc[mi][ni][0], acc[mi][ni][1]);
        }
        if (r1 < M_NODES) {
            __half* dst = msg + (size_t)r1 * NMSG + cb;
#pragma unroll
            for (int ni = 0; ni < 8; ni++)
                *(__half2*)(dst + ni * 8) = __floats2half2_rn(acc[mi][ni][2], acc[mi][ni][3]);
        }
    }
}

// ---------------- scatter: acc[tgt] += msg_fp16[src, r*256 : +256]  (float4 red) ----------------
__global__ void scatter_kernel(const int* __restrict__ edges, const __half* __restrict__ msg,
                               float* __restrict__ acc)
{
    int e = blockIdx.x * 4 + (threadIdx.x >> 6);
    int q = threadIdx.x & 63;
    int r = e / EPR, idx = e % EPR;
    int src = edges[r * 2 * EPR + idx];
    int tgt = edges[r * 2 * EPR + EPR + idx];
    const __half2* p2 = (const __half2*)(msg + (size_t)src * NMSG + r * HID + q * 4);
    float2 v0 = __half22float2(p2[0]);
    float2 v1 = __half22float2(p2[1]);
    float* p = acc + (size_t)tgt * HID + q * 4;
    asm volatile("red.global.add.v4.f32 [%0], {%1, %2, %3, %4};"
                 :: "l"(p), "f"(v0.x), "f"(v0.y), "f"(v1.x), "f"(v1.y) : "memory");
}

// ---------------- combine: h_next(fp16) = relu(acc*invdeg + msg_self + bias) ----------------
__global__ void combine_kernel(const float* __restrict__ acc, const __half* __restrict__ msg,
                               const float* __restrict__ invd, const float* __restrict__ bias,
                               __half* __restrict__ hout)
{
    int gid = blockIdx.x * 256 + threadIdx.x;      // float4 group over M*64
    if (gid < M_NODES * (HID / 4)) {
        int n = gid >> 6, q = gid & 63;
        float w = invd[n];
        float4 a = *(const float4*)(acc + (size_t)gid * 4);
        const __half2* s2 = (const __half2*)(msg + (size_t)n * NMSG + 1536 + q * 4);
        float2 s0 = __half22float2(s2[0]);
        float2 s1 = __half22float2(s2[1]);
        float4 bb = *(const float4*)(bias + q * 4);
        __half2 o0 = __floats2half2_rn(fmaxf(a.x * w + s0.x + bb.x, 0.f),
                                       fmaxf(a.y * w + s0.y + bb.y, 0.f));
        __half2 o1 = __floats2half2_rn(fmaxf(a.z * w + s1.x + bb.z, 0.f),
                                       fmaxf(a.w * w + s1.y + bb.w, 0.f));
        __half2* dst = (__half2*)(hout + (size_t)gid * 4);
        dst[0] = o0; dst[1] = o1;
    }
}

// ---------------- pooling + MLP ----------------
__global__ void count_kernel(const int* __restrict__ bids, int* __restrict__ counts)
{
    int g = threadIdx.x;
    if (g >= NGRAPH) return;
    int lo = 0, hi = M_NODES;
    while (lo < hi) { int mid = (lo + hi) >> 1; if (bids[mid] < g) lo = mid + 1; else hi = mid; }
    int start = lo;
    lo = 0; hi = M_NODES;
    while (lo < hi) { int mid = (lo + hi) >> 1; if (bids[mid] <= g) lo = mid + 1; else hi = mid; }
    counts[g] = lo - start;
}

__global__ void pool_sum_kernel(const __half* __restrict__ h, const int* __restrict__ bids,
                                float* __restrict__ pooled)
{
    int c = threadIdx.x;
    int n_start = blockIdx.x * 256;
    int n_end = n_start + 256;
    if (n_end > M_NODES) n_end = M_NODES;
    if (n_start >= M_NODES) return;
    int cur = bids[n_start];
    float acc = 0.0f;
    for (int n = n_start; n < n_end; n++) {
        int g = bids[n];
        if (g != cur) { atomicAdd(&pooled[cur * HID + c], acc); acc = 0.0f; cur = g; }
        acc += __half2float(h[(size_t)n * HID + c]);
    }
    atomicAdd(&pooled[cur * HID + c], acc);
}

__global__ void mlp_kernel(const float* __restrict__ pooled, const int* __restrict__ counts,
                           const float* __restrict__ pW1, const float* __restrict__ pb1,
                           const float* __restrict__ pW2, const float* __restrict__ pb2,
                           float* __restrict__ out)
{
    __shared__ float p[HID];
    __shared__ float t[HID];
    int g = blockIdx.x, d = threadIdx.x;
    int cn = counts[g];
    float inv = 1.0f / (float)(cn > 1 ? cn : 1);
    p[d] = pooled[g * HID + d] * inv;
    __syncthreads();
    float a = pb1[d];
#pragma unroll 8
    for (int k = 0; k < HID; k++) a += p[k] * pW1[k * HID + d];
    t[d] = a > 0.f ? a : 0.f;
    __syncthreads();
    float o = pb2[d];
#pragma unroll 8
    for (int k = 0; k < HID; k++) o += t[k] * pW2[k * HID + d];
    out[g * HID + d] = o;
}

// ---------------------------------------------------------------
extern "C" void kernel_launch(void* const* d_in, const int* in_sizes, int n_in,
                              void* d_out, int out_size)
{
    const int*   x_type = (const int*)d_in[0];
    const int*   x_sub  = (const int*)d_in[1];
    const int*   edges  = (const int*)d_in[2];
    const int*   bids   = (const int*)d_in[3];
    const float* temb   = (const float*)d_in[5];
    const float* semb   = (const float*)d_in[6];
    const float* Wrel0  = (const float*)d_in[7];
    const float* Wself0 = (const float*)d_in[8];
    const float* b0     = (const float*)d_in[9];
    const float* Wrel1  = (const float*)d_in[10];
    const float* Wself1 = (const float*)d_in[11];
    const float* b1     = (const float*)d_in[12];
    const float* pW1    = (const float*)d_in[13];
    const float* pb1    = (const float*)d_in[14];
    const float* pW2    = (const float*)d_in[15];
    const float* pb2    = (const float*)d_in[16];
    float* out = (float*)d_out;

    void *phA, *phB, *pmsg, *pacc, *pWt, *pinv, *pdeg, *ppooled, *pcnt;
    cudaGetSymbolAddress(&phA, g_hA16);
    cudaGetSymbolAddress(&phB, g_hB16);
    cudaGetSymbolAddress(&pmsg, g_msg);
    cudaGetSymbolAddress(&pacc, g_acc);
    cudaGetSymbolAddress(&pWt, g_Wt);
    cudaGetSymbolAddress(&pinv, g_invdeg);
    cudaGetSymbolAddress(&pdeg, g_deg);
    cudaGetSymbolAddress(&ppooled, g_pooled);
    cudaGetSymbolAddress(&pcnt, g_counts);

    cudaFuncSetAttribute(gemm_mma, cudaFuncAttributeMaxDynamicSharedMemorySize, GSMEM);

    cudaMemsetAsync(pdeg, 0, M_NODES * sizeof(int));
    cudaMemsetAsync(ppooled, 0, NGRAPH * HID * sizeof(float));

    embed_kernel<<<(M_NODES * HID + 255) / 256, 256>>>(x_type, x_sub, temb, semb, (__half*)phA);
    degree_kernel<<<(NEDGE + 255) / 256, 256>>>(edges, (int*)pdeg);
    invdeg_kernel<<<(M_NODES + 255) / 256, 256>>>((const int*)pdeg, (float*)pinv);

    dim3 ggrid(NMSG / BN, (M_NODES + BM - 1) / BM);   // (14, 782)

    // ---- layer 0: hA -> hB ----
    convW_kernel<<<(NMSG * HID + 255) / 256, 256>>>(Wrel0, Wself0, (__half*)pWt);
    gemm_mma<<<ggrid, 256, GSMEM>>>((const __half*)phA, (const __half*)pWt, (__half*)pmsg);
    cudaMemsetAsync(pacc, 0, (size_t)M_NODES * HID * sizeof(float));
    scatter_kernel<<<NEDGE / 4, 256>>>(edges, (const __half*)pmsg, (float*)pacc);
    combine_kernel<<<(M_NODES * (HID / 4) + 255) / 256, 256>>>((const float*)pacc, (const __half*)pmsg,
                                                               (const float*)pinv, b0, (__half*)phB);

    // ---- layer 1: hB -> hA ----
    convW_kernel<<<(NMSG * HID + 255) / 256, 256>>>(Wrel1, Wself1, (__half*)pWt);
    gemm_mma<<<ggrid, 256, GSMEM>>>((const __half*)phB, (const __half*)pWt, (__half*)pmsg);
    cudaMemsetAsync(pacc, 0, (size_t)M_NODES * HID * sizeof(float));
    scatter_kernel<<<NEDGE / 4, 256>>>(edges, (const __half*)pmsg, (float*)pacc);
    combine_kernel<<<(M_NODES * (HID / 4) + 255) / 256, 256>>>((const float*)pacc, (const __half*)pmsg,
                                                               (const float*)pinv, b1, (__half*)phA);

    // ---- pool + MLP ----
    count_kernel<<<1, 128>>>(bids, (int*)pcnt);
    pool_sum_kernel<<<(M_NODES + 255) / 256, 256>>>((const __half*)phA, bids, (float*)ppooled);
    mlp_kernel<<<NGRAPH, 256>>>((const float*)ppooled, (const int*)pcnt, pW1, pb1, pW2, pb2, out);
}

// round 5
// speedup vs baseline: 5.9304x; 1.2494x over previous
#include <cuda_runtime.h>
#include <cuda_fp16.h>

#define M_NODES 100000
#define HID     256
#define NREL    6
#define EPR     100000
#define NEDGE   (NREL * EPR)        // 600000
#define NMSG    1792                // 6*256 rel msgs + 256 self
#define NGRAPH  128

#define BM 128
#define BN 128
#define BK 64
#define NCHUNK (HID / BK)           // 4
#define GSMEM  (2 * (BM + BN) * BK * 2)   // 65536

// ---------------- scratch (device globals; no allocation allowed) ----------------
__device__ __half  g_hA16[(size_t)M_NODES * HID];      // 51.2 MB
__device__ __half  g_hB16[(size_t)M_NODES * HID];      // 51.2 MB
__device__ __half  g_msg[(size_t)M_NODES * NMSG];      // 358.4 MB
__device__ __half  g_Wt[NMSG * HID];
__device__ float   g_invdeg[M_NODES];
__device__ int     g_deg[M_NODES];
__device__ int     g_off[M_NODES + 1];
__device__ int     g_cursor[M_NODES];
__device__ int     g_eidx[NEDGE];                      // packed (src<<3)|r, grouped by tgt
__device__ float   g_pooled[NGRAPH * HID];
__device__ int     g_counts[NGRAPH];

// ---------------- PTX helpers (baseline ISA; nothing 'a'-gated) ----------------
__device__ __forceinline__ unsigned su32(const void* p) {
    return (unsigned)__cvta_generic_to_shared(p);
}
__device__ __forceinline__ void cp16(void* sm, const void* gm) {
    asm volatile("cp.async.cg.shared.global [%0], [%1], 16;" :: "r"(su32(sm)), "l"(gm));
}
#define CP_COMMIT() asm volatile("cp.async.commit_group;" ::: "memory")
#define CP_WAIT(n)  asm volatile("cp.async.wait_group %0;" :: "n"(n) : "memory")

__device__ __forceinline__ void ldsm4(unsigned* r, unsigned addr) {
    asm volatile("ldmatrix.sync.aligned.m8n8.x4.shared.b16 {%0,%1,%2,%3}, [%4];"
                 : "=r"(r[0]), "=r"(r[1]), "=r"(r[2]), "=r"(r[3]) : "r"(addr));
}
__device__ __forceinline__ void mma16816(float* c, const unsigned* a, unsigned b0, unsigned b1) {
    asm volatile("mma.sync.aligned.m16n8k16.row.col.f32.f16.f16.f32 "
                 "{%0,%1,%2,%3}, {%4,%5,%6,%7}, {%8,%9}, {%0,%1,%2,%3};"
                 : "+f"(c[0]), "+f"(c[1]), "+f"(c[2]), "+f"(c[3])
                 : "r"(a[0]), "r"(a[1]), "r"(a[2]), "r"(a[3]), "r"(b0), "r"(b1));
}
__device__ __forceinline__ unsigned swz(unsigned off) {
    return off ^ ((off >> 3) & 0x70);
}

// ---------------- small kernels ----------------
__global__ void embed_kernel(const int* __restrict__ x_type, const int* __restrict__ x_sub,
                             const float* __restrict__ temb, const float* __restrict__ semb,
                             __half* __restrict__ h0)
{
    int gid = blockIdx.x * 256 + threadIdx.x;
    if (gid < M_NODES * HID) {
        int n = gid >> 8, c = gid & 255;
        float v = (c < 128) ? temb[x_type[n] * 128 + c] : semb[x_sub[n] * 128 + (c - 128)];
        h0[gid] = __float2half_rn(v);
    }
}

__global__ void degree_kernel(const int* __restrict__ edges, int* __restrict__ deg)
{
    int i = blockIdx.x * 256 + threadIdx.x;
    if (i < NEDGE) {
        int r = i / EPR, e = i % EPR;
        atomicAdd(&deg[edges[r * 2 * EPR + EPR + e]], 1);
    }
}

__global__ void invdeg_kernel(const int* __restrict__ deg, float* __restrict__ invd)
{
    int i = blockIdx.x * 256 + threadIdx.x;
    if (i < M_NODES) {
        int d = deg[i];
        invd[i] = 1.0f / (float)(d > 1 ? d : 1);
    }
}

// exclusive scan of deg -> off (single block, 1024 threads, shuffle-based)
__global__ void scan_kernel(const int* __restrict__ deg, int* __restrict__ off)
{
    __shared__ int wsum[32];
    __shared__ int wbase[32];
    __shared__ int carry_sh;
    const int tid = threadIdx.x, lane = tid & 31, wid = tid >> 5;
    if (tid == 0) carry_sh = 0;
    __syncthreads();
    for (int base = 0; base < M_NODES; base += 1024) {
        int i = base + tid;
        int v = (i < M_NODES) ? deg[i] : 0;
        int x = v;
#pragma unroll
        for (int o = 1; o < 32; o <<= 1) {
            int t = __shfl_up_sync(0xffffffff, x, o);
            if (lane >= o) x += t;
        }
        if (lane == 31) wsum[wid] = x;
        int carry = carry_sh;
        __syncthreads();
        if (wid == 0) {
            int s = wsum[lane];
            int y = s;
#pragma unroll
            for (int o = 1; o < 32; o <<= 1) {
                int t = __shfl_up_sync(0xffffffff, y, o);
                if (lane >= o) y += t;
            }
            wbase[lane] = y - s;
            if (lane == 31) carry_sh = carry + y;
        }
        __syncthreads();
        if (i < M_NODES) off[i] = carry + wbase[wid] + x - v;
    }
    if (tid == 0) off[M_NODES] = carry_sh;
}

// fill CSR slots: eidx grouped by tgt, payload = (src<<3)|r
__global__ void fill_kernel(const int* __restrict__ edges, const int* __restrict__ off,
                            int* __restrict__ cursor, int* __restrict__ eidx)
{
    int i = blockIdx.x * 256 + threadIdx.x;
    if (i < NEDGE) {
        int r = i / EPR, e = i % EPR;
        int src = edges[r * 2 * EPR + e];
        int tgt = edges[r * 2 * EPR + EPR + e];
        int slot = off[tgt] + atomicAdd(&cursor[tgt], 1);
        eidx[slot] = (src << 3) | r;
    }
}

// ---------------- HMMA GEMM: msg[M,1792] (fp16) = h[M,256] @ Wcat, fp32 accum ----------------
__global__ __launch_bounds__(256, 2)
void gemm_mma(const __half* __restrict__ A, const __half* __restrict__ Wt,
              __half* __restrict__ msg)
{
    extern __shared__ unsigned char smraw[];
    const int tid  = threadIdx.x;
    const int lane = tid & 31;
    const int wid  = tid >> 5;
    const int wm   = wid & 3;
    const int wn   = wid >> 2;
    const int m0   = blockIdx.y * BM;
    const int n0   = blockIdx.x * BN;

    const int lrow = tid >> 3;
    const int lseg = tid & 7;

    int amrow[4];
#pragma unroll
    for (int p = 0; p < 4; p++) {
        int m = m0 + lrow + p * 32;
        amrow[p] = m < M_NODES ? m : M_NODES - 1;
    }

    float acc[2][8][4];
#pragma unroll
    for (int mi = 0; mi < 2; mi++)
#pragma unroll
        for (int ni = 0; ni < 8; ni++)
#pragma unroll
            for (int j = 0; j < 4; j++) acc[mi][ni][j] = 0.0f;

    unsigned aS[2], bS[2];
    aS[0] = su32(smraw);            bS[0] = su32(smraw + 16384);
    aS[1] = su32(smraw + 32768);    bS[1] = su32(smraw + 49152);

    auto issue = [&](int c, int st) {
        int koff = c * BK;
        unsigned char* As = smraw + st * 32768;
        unsigned char* Bs = smraw + st * 32768 + 16384;
#pragma unroll
        for (int p = 0; p < 4; p++) {
            int row = lrow + p * 32;
            unsigned so = swz((unsigned)(row * 128 + lseg * 16));
            cp16(As + so, A  + (size_t)amrow[p] * HID + koff + lseg * 8);
            cp16(Bs + so, Wt + (size_t)(n0 + row) * HID + koff + lseg * 8);
        }
        CP_COMMIT();
    };

    issue(0, 0);

    for (int c = 0; c < NCHUNK; ++c) {
        int st = c & 1;
        if (c + 1 < NCHUNK) { issue(c + 1, st ^ 1); CP_WAIT(1); }
        else                { CP_WAIT(0); }
        __syncthreads();

        unsigned ab = aS[st], bb = bS[st];
#pragma unroll
        for (int ks = 0; ks < 4; ++ks) {
            unsigned a[2][4], b[4][4];
#pragma unroll
            for (int mi = 0; mi < 2; mi++) {
                int row = wm * 32 + mi * 16 + (lane & 15);
                unsigned off = (unsigned)(row * 128 + ks * 32 + (lane >> 4) * 16);
                ldsm4(a[mi], ab + swz(off));
            }
#pragma unroll
            for (int nj = 0; nj < 4; nj++) {
                int q = lane >> 3, r = lane & 7;
                int nrow = wn * 64 + nj * 16 + (q >> 1) * 8 + r;
                unsigned off = (unsigned)(nrow * 128 + ks * 32 + (q & 1) * 16);
                ldsm4(b[nj], bb + swz(off));
            }
#pragma unroll
            for (int mi = 0; mi < 2; mi++)
#pragma unroll
                for (int ni = 0; ni < 8; ni++)
                    mma16816(acc[mi][ni], a[mi], b[ni >> 1][(ni & 1) * 2], b[ni >> 1][(ni & 1) * 2 + 1]);
        }
        __syncthreads();
    }

    const int cb = n0 + wn * 64 + (lane & 3) * 2;
#pragma unroll
    for (int mi = 0; mi < 2; mi++) {
        int r0 = m0 + wm * 32 + mi * 16 + (lane >> 2);
        int r1 = r0 + 8;
        if (r0 < M_NODES) {
            __half* dst = msg + (size_t)r0 * NMSG + cb;
#pragma unroll
            for (int ni = 0; ni < 8; ni++)
                *(__half2*)(dst + ni * 8) = __floats2half2_rn(acc[mi][ni][0], acc[mi][ni][1]);
        }
        if (r1 < M_NODES) {
            __half* dst = msg + (size_t)r1 * NMSG + cb;
#pragma unroll
            for (int ni = 0; ni < 8; ni++)
                *(__half2*)(dst + ni * 8) = __floats2half2_rn(acc[mi][ni][2], acc[mi][ni][3]);
        }
    }
}

// ---------------- gather + combine: warp per node ----------------
// h_next[node] = relu( (1/deg) * sum_e msg[src_e, r_e*256:+256] + msg[node,1536:+256] + bias )
__global__ __launch_bounds__(256)
void gather_kernel(const __half* __restrict__ msg, const int* __restrict__ off,
                   const int* __restrict__ eidx, const float* __restrict__ invd,
                   const float* __restrict__ bias, __half* __restrict__ hout)
{
    int node = blockIdx.x * 8 + (threadIdx.x >> 5);
    if (node >= M_NODES) return;
    const int lane = threadIdx.x & 31;

    int beg = __ldg(&off[node]);
    int end = __ldg(&off[node + 1]);

    float acc[8];
#pragma unroll
    for (int j = 0; j < 8; j++) acc[j] = 0.0f;

    auto accum = [&](uint4 u) {
        const __half2* h2 = (const __half2*)&u;
#pragma unroll
        for (int k = 0; k < 4; k++) {
            float2 f = __half22float2(h2[k]);
            acc[2 * k]     += f.x;
            acc[2 * k + 1] += f.y;
        }
    };

    int e = beg;
    for (; e + 1 < end; e += 2) {          // unroll x2 for MLP
        int pk0 = __ldg(&eidx[e]);
        int pk1 = __ldg(&eidx[e + 1]);
        uint4 u0 = *(const uint4*)(msg + (size_t)(pk0 >> 3) * NMSG + (pk0 & 7) * HID + lane * 8);
        uint4 u1 = *(const uint4*)(msg + (size_t)(pk1 >> 3) * NMSG + (pk1 & 7) * HID + lane * 8);
        accum(u0);
        accum(u1);
    }
    if (e < end) {
        int pk = __ldg(&eidx[e]);
        uint4 u = *(const uint4*)(msg + (size_t)(pk >> 3) * NMSG + (pk & 7) * HID + lane * 8);
        accum(u);
    }

    float w = invd[node];
    uint4 s = *(const uint4*)(msg + (size_t)node * NMSG + 1536 + lane * 8);
    const __half2* s2 = (const __half2*)&s;
    float4 b0 = *(const float4*)(bias + lane * 8);
    float4 b1 = *(const float4*)(bias + lane * 8 + 4);
    float bb[8] = {b0.x, b0.y, b0.z, b0.w, b1.x, b1.y, b1.z, b1.w};

    uint4 outv;
    __half2* o2 = (__half2*)&outv;
#pragma unroll
    for (int k = 0; k < 4; k++) {
        float2 sf = __half22float2(s2[k]);
        float v0 = fmaxf(acc[2 * k]     * w + sf.x + bb[2 * k],     0.f);
        float v1 = fmaxf(acc[2 * k + 1] * w + sf.y + bb[2 * k + 1], 0.f);
        o2[k] = __floats2half2_rn(v0, v1);
    }
    *(uint4*)(hout + (size_t)node * HID + lane * 8) = outv;
}

// Wt[n][k] fp16
__global__ void convW_kernel(const float* __restrict__ Wrel, const float* __restrict__ Wself,
                             __half* __restrict__ Wt)
{
    int idx = blockIdx.x * 256 + threadIdx.x;
    if (idx < NMSG * HID) {
        int n = idx >> 8, k = idx & 255;
        float v = (n < 1536) ? Wrel[(((n >> 8) * 256) + k) * 256 + (n & 255)]
                             : Wself[k * 256 + (n & 255)];
        Wt[idx] = __float2half_rn(v);
    }
}

// ---------------- pooling + MLP ----------------
__global__ void count_kernel(const int* __restrict__ bids, int* __restrict__ counts)
{
    int g = threadIdx.x;
    if (g >= NGRAPH) return;
    int lo = 0, hi = M_NODES;
    while (lo < hi) { int mid = (lo + hi) >> 1; if (bids[mid] < g) lo = mid + 1; else hi = mid; }
    int start = lo;
    lo = 0; hi = M_NODES;
    while (lo < hi) { int mid = (lo + hi) >> 1; if (bids[mid] <= g) lo = mid + 1; else hi = mid; }
    counts[g] = lo - start;
}

__global__ void pool_sum_kernel(const __half* __restrict__ h, const int* __restrict__ bids,
                                float* __restrict__ pooled)
{
    int c = threadIdx.x;
    int n_start = blockIdx.x * 256;
    int n_end = n_start + 256;
    if (n_end > M_NODES) n_end = M_NODES;
    if (n_start >= M_NODES) return;
    int cur = bids[n_start];
    float acc = 0.0f;
    for (int n = n_start; n < n_end; n++) {
        int g = bids[n];
        if (g != cur) { atomicAdd(&pooled[cur * HID + c], acc); acc = 0.0f; cur = g; }
        acc += __half2float(h[(size_t)n * HID + c]);
    }
    atomicAdd(&pooled[cur * HID + c], acc);
}

__global__ void mlp_kernel(const float* __restrict__ pooled, const int* __restrict__ counts,
                           const float* __restrict__ pW1, const float* __restrict__ pb1,
                           const float* __restrict__ pW2, const float* __restrict__ pb2,
                           float* __restrict__ out)
{
    __shared__ float p[HID];
    __shared__ float t[HID];
    int g = blockIdx.x, d = threadIdx.x;
    int cn = counts[g];
    float inv = 1.0f / (float)(cn > 1 ? cn : 1);
    p[d] = pooled[g * HID + d] * inv;
    __syncthreads();
    float a = pb1[d];
#pragma unroll 8
    for (int k = 0; k < HID; k++) a += p[k] * pW1[k * HID + d];
    t[d] = a > 0.f ? a : 0.f;
    __syncthreads();
    float o = pb2[d];
#pragma unroll 8
    for (int k = 0; k < HID; k++) o += t[k] * pW2[k * HID + d];
    out[g * HID + d] = o;
}

// ---------------------------------------------------------------
extern "C" void kernel_launch(void* const* d_in, const int* in_sizes, int n_in,
                              void* d_out, int out_size)
{
    const int*   x_type = (const int*)d_in[0];
    const int*   x_sub  = (const int*)d_in[1];
    const int*   edges  = (const int*)d_in[2];
    const int*   bids   = (const int*)d_in[3];
    const float* temb   = (const float*)d_in[5];
    const float* semb   = (const float*)d_in[6];
    const float* Wrel0  = (const float*)d_in[7];
    const float* Wself0 = (const float*)d_in[8];
    const float* b0     = (const float*)d_in[9];
    const float* Wrel1  = (const float*)d_in[10];
    const float* Wself1 = (const float*)d_in[11];
    const float* b1     = (const float*)d_in[12];
    const float* pW1    = (const float*)d_in[13];
    const float* pb1    = (const float*)d_in[14];
    const float* pW2    = (const float*)d_in[15];
    const float* pb2    = (const float*)d_in[16];
    float* out = (float*)d_out;

    void *phA, *phB, *pmsg, *pWt, *pinv, *pdeg, *poff, *pcur, *peidx, *ppooled, *pcnt;
    cudaGetSymbolAddress(&phA, g_hA16);
    cudaGetSymbolAddress(&phB, g_hB16);
    cudaGetSymbolAddress(&pmsg, g_msg);
    cudaGetSymbolAddress(&pWt, g_Wt);
    cudaGetSymbolAddress(&pinv, g_invdeg);
    cudaGetSymbolAddress(&pdeg, g_deg);
    cudaGetSymbolAddress(&poff, g_off);
    cudaGetSymbolAddress(&pcur, g_cursor);
    cudaGetSymbolAddress(&peidx, g_eidx);
    cudaGetSymbolAddress(&ppooled, g_pooled);
    cudaGetSymbolAddress(&pcnt, g_counts);

    cudaFuncSetAttribute(gemm_mma, cudaFuncAttributeMaxDynamicSharedMemorySize, GSMEM);

    cudaMemsetAsync(pdeg, 0, M_NODES * sizeof(int));
    cudaMemsetAsync(pcur, 0, M_NODES * sizeof(int));
    cudaMemsetAsync(ppooled, 0, NGRAPH * HID * sizeof(float));

    embed_kernel<<<(M_NODES * HID + 255) / 256, 256>>>(x_type, x_sub, temb, semb, (__half*)phA);
    degree_kernel<<<(NEDGE + 255) / 256, 256>>>(edges, (int*)pdeg);
    invdeg_kernel<<<(M_NODES + 255) / 256, 256>>>((const int*)pdeg, (float*)pinv);
    scan_kernel<<<1, 1024>>>((const int*)pdeg, (int*)poff);
    fill_kernel<<<(NEDGE + 255) / 256, 256>>>(edges, (const int*)poff, (int*)pcur, (int*)peidx);

    dim3 ggrid(NMSG / BN, (M_NODES + BM - 1) / BM);   // (14, 782)
    int gblocks = (M_NODES + 7) / 8;

    // ---- layer 0: hA -> hB ----
    convW_kernel<<<(NMSG * HID + 255) / 256, 256>>>(Wrel0, Wself0, (__half*)pWt);
    gemm_mma<<<ggrid, 256, GSMEM>>>((const __half*)phA, (const __half*)pWt, (__half*)pmsg);
    gather_kernel<<<gblocks, 256>>>((const __half*)pmsg, (const int*)poff, (const int*)peidx,
                                    (const float*)pinv, b0, (__half*)phB);

    // ---- layer 1: hB -> hA ----
    convW_kernel<<<(NMSG * HID + 255) / 256, 256>>>(Wrel1, Wself1, (__half*)pWt);
    gemm_mma<<<ggrid, 256, GSMEM>>>((const __half*)phB, (const __half*)pWt, (__half*)pmsg);
    gather_kernel<<<gblocks, 256>>>((const __half*)pmsg, (const int*)poff, (const int*)peidx,
                                    (const float*)pinv, b1, (__half*)phA);

    // ---- pool + MLP ----
    count_kernel<<<1, 128>>>(bids, (int*)pcnt);
    pool_sum_kernel<<<(M_NODES + 255) / 256, 256>>>((const __half*)phA, bids, (float*)ppooled);
    mlp_kernel<<<NGRAPH, 256>>>((const float*)ppooled, (const int*)pcnt, pW1, pb1, pW2, pb2, out);
}